// round 10
// baseline (speedup 1.0000x reference)
#include <cuda_runtime.h>
#include <cstdint>

#define NPIX 65536
#define DDIM 256
#define KCODES 512
#define MT 128
#define THREADS 256
#define ZS 268                // z_s row stride (floats)
#define Z_OFF 0
#define B_OFF 34304           // 2 x 8192-float cp.async buffers
#define ZSQ_OFF 50688
#define ESQ_OFF 50816
#define SMEM_FLOATS 51328     // 205,312 bytes
#define EPS 2e-4f             // candidate window (provable bound ~6.6e-5)

__device__ float g_esq[KCODES];
// B fragments: [tt(32)][ks(8)][nt8(8)][lane(32)][bh0,bh1,bl0,bl1]
__device__ __align__(16) float e_frag[32 * 8192];

static __device__ __forceinline__ uint32_t smem_u32(const void* p) {
    uint32_t a;
    asm("{ .reg .u64 t; cvta.to.shared.u64 t, %1; cvt.u32.u64 %0, t; }" : "=r"(a) : "l"(p));
    return a;
}
static __device__ __forceinline__ uint32_t f2tf32(float v) {
    uint32_t r;
    asm("cvt.rna.tf32.f32 %0, %1;" : "=r"(r) : "f"(v));
    return r;
}
static __device__ __forceinline__ void mma_tf32(float* c, const uint32_t* a,
                                                uint32_t b0, uint32_t b1) {
    asm volatile("mma.sync.aligned.m16n8k8.row.col.f32.tf32.tf32.f32 "
                 "{%0,%1,%2,%3}, {%4,%5,%6,%7}, {%8,%9}, {%0,%1,%2,%3};"
                 : "+f"(c[0]), "+f"(c[1]), "+f"(c[2]), "+f"(c[3])
                 : "r"(a[0]), "r"(a[1]), "r"(a[2]), "r"(a[3]), "r"(b0), "r"(b1));
}
#define CP_ASYNC16(saddr, gptr) \
    asm volatile("cp.async.ca.shared.global [%0], [%1], 16;" :: "r"(saddr), "l"(gptr))
#define CP_COMMIT()  asm volatile("cp.async.commit_group;" ::: "memory")
#define CP_WAIT0()   asm volatile("cp.async.wait_group 0;" ::: "memory")

// ---- prep: esq (reference rounding order) + scatter codebook into B-fragment images ----
__global__ void prep_kernel(const float* __restrict__ cb) {
    int n = blockIdx.x * blockDim.x + threadIdx.x;
    if (n >= KCODES) return;
    const float4* row = (const float4*)(cb + n * DDIM);
    float sx = 0.f, sy = 0.f, sz = 0.f, sw = 0.f;
#pragma unroll
    for (int i = 0; i < DDIM / 4; i++) {
        float4 v = row[i];
        sx = __fadd_rn(sx, __fmul_rn(v.x, v.x));
        sy = __fadd_rn(sy, __fmul_rn(v.y, v.y));
        sz = __fadd_rn(sz, __fmul_rn(v.z, v.z));
        sw = __fadd_rn(sw, __fmul_rn(v.w, v.w));
    }
    g_esq[n] = __fadd_rn(__fadd_rn(sx, sy), __fadd_rn(sz, sw));

    const int g = n & 7, nt8 = (n >> 3) & 7, nchq = (n >> 6) * 4;
    for (int d = 0; d < DDIM; d++) {
        float v = cb[n * DDIM + d];
        uint32_t hb = f2tf32(v);
        float hf = __uint_as_float(hb);
        uint32_t lb = f2tf32(v - hf);
        int tt = nchq + (d >> 6);
        int ks = (d >> 3) & 7;
        int ko = d & 7, tig = ko & 3, kh = ko >> 2;
        int lane = g * 4 + tig;
        int base = tt * 8192 + ((ks * 8 + nt8) * 32 + lane) * 4;
        e_frag[base + kh]     = __uint_as_float(hb);
        e_frag[base + 2 + kh] = __uint_as_float(lb);
    }
}

__global__ __launch_bounds__(THREADS, 1)
void vq_mma_kernel(const float* __restrict__ z, const float* __restrict__ cb,
                   float* __restrict__ out) {
    extern __shared__ __align__(16) float smem[];
    float* z_s   = smem + Z_OFF;
    float* bbuf  = smem + B_OFF;
    float* zsq_s = smem + ZSQ_OFF;
    float* esq_s = smem + ESQ_OFF;
    const uint32_t bbuf_s = smem_u32(bbuf);

    const int tid  = threadIdx.x;
    const int warp = tid >> 5;
    const int lane = tid & 31;
    const int g    = lane >> 2;      // 0..7
    const int tig  = lane & 3;       // 0..3
    const int wm   = warp & 3;       // M-warp 0..3 -> mtiles {wm, wm+4}
    const int wn   = warp >> 2;      // N-warp 0..1 -> ntiles {wn*4..wn*4+3}

    const int pix_base = blockIdx.x * MT;
    const float* zbase = z + (size_t)(pix_base >> 10) * (DDIM * 1024) + (pix_base & 1023);

    // ---- transpose z: gmem [d][px] -> z_s[px][d] via staged buffer (stride 132) ----
    float* stage = bbuf;
    for (int db = 0; db < 8; db++) {
        const int dblk = db * 32;
        __syncthreads();
#pragma unroll
        for (int it = 0; it < 4; it++) {
            int linear = tid + THREADS * it;
            int d  = linear >> 5;
            int p4 = (linear & 31) << 2;
            float4 v = *(const float4*)(zbase + (size_t)(dblk + d) * 1024 + p4);
            *(float4*)(stage + d * 132 + p4) = v;
        }
        __syncthreads();
#pragma unroll
        for (int it = 0; it < 4; it++) {
            int linear = tid + THREADS * it;
            int p   = linear & 127;
            int dl4 = (linear >> 7) << 2;
            float4 w;
            w.x = stage[(dl4 + 0) * 132 + p];
            w.y = stage[(dl4 + 1) * 132 + p];
            w.z = stage[(dl4 + 2) * 132 + p];
            w.w = stage[(dl4 + 3) * 132 + p];
            *(float4*)(z_s + p * ZS + dblk + dl4) = w;
        }
    }
    __syncthreads();

    // ---- zsq (proven rounding order) + esq into smem ----
    esq_s[tid]       = g_esq[tid];
    esq_s[tid + 256] = g_esq[tid + 256];
    if (tid < MT) {
        const float4* zr = (const float4*)(z_s + tid * ZS);
        float sx = 0.f, sy = 0.f, sz = 0.f, sw = 0.f;
#pragma unroll
        for (int i = 0; i < DDIM / 4; i++) {
            float4 v = zr[i];
            sx = __fadd_rn(sx, __fmul_rn(v.x, v.x));
            sy = __fadd_rn(sy, __fmul_rn(v.y, v.y));
            sz = __fadd_rn(sz, __fmul_rn(v.z, v.z));
            sw = __fadd_rn(sw, __fmul_rn(v.w, v.w));
        }
        zsq_s[tid] = __fadd_rn(__fadd_rn(sx, sy), __fadd_rn(sz, sw));
    }

    // ---- prefetch B block 0 via cp.async ----
#pragma unroll
    for (int it = 0; it < 8; it++) {
        int fo = tid * 4 + it * 1024;
        CP_ASYNC16(bbuf_s + fo * 4, (const void*)(e_frag + fo));
    }
    CP_COMMIT();
    __syncthreads();

    // per-slot best2: slots s = 0..3 are (m, pixel-half); codes of slot partition by (wn,tig)
    float d1[4], d2[4];
    int   i1[4], i2[4];
    float acc[2][4][4];
#pragma unroll
    for (int s = 0; s < 4; s++) { d1[s] = 3.4e38f; d2[s] = 3.4e38f; i1[s] = 0; i2[s] = 0; }
#pragma unroll
    for (int m = 0; m < 2; m++)
#pragma unroll
        for (int j = 0; j < 4; j++)
#pragma unroll
            for (int r = 0; r < 4; r++) acc[m][j][r] = 0.f;

    for (int t = 0; t < 32; t++) {
        const int buf = t & 1;
        CP_WAIT0();
        __syncthreads();
        if (t + 1 < 32) {
#pragma unroll
            for (int it = 0; it < 8; it++) {
                int fo = tid * 4 + it * 1024;
                CP_ASYNC16(bbuf_s + ((buf ^ 1) * 8192 + fo) * 4,
                           (const void*)(e_frag + (t + 1) * 8192 + fo));
            }
            CP_COMMIT();
        }

        const int kblk = (t & 3) * 64;
#pragma unroll
        for (int ks = 0; ks < 8; ks++) {
            const int kbase = kblk + ks * 8;
            uint32_t ah[2][4], al[2][4];
#pragma unroll
            for (int m = 0; m < 2; m++) {
                const int mrow = (wm + m * 4) * 16;
#pragma unroll
                for (int r = 0; r < 4; r++) {
                    float v = z_s[(mrow + g + (r & 1) * 8) * ZS +
                                  kbase + tig + (r >> 1) * 4];
                    uint32_t hb = f2tf32(v);
                    ah[m][r] = hb;
                    al[m][r] = f2tf32(v - __uint_as_float(hb));
                }
            }
#pragma unroll
            for (int j = 0; j < 4; j++) {
                const int nt8 = wn * 4 + j;
                uint4 bv = *(const uint4*)(bbuf + (buf * 8192) +
                                           ((ks * 8 + nt8) * 32 + lane) * 4);
#pragma unroll
                for (int m = 0; m < 2; m++) {
                    mma_tf32(acc[m][j], ah[m], bv.x, bv.y);  // hi*hi
                    mma_tf32(acc[m][j], ah[m], bv.z, bv.w);  // hi*lo
                    mma_tf32(acc[m][j], al[m], bv.x, bv.y);  // lo*hi
                }
            }
        }

        // ---- end of nch: fold this K-chunk's dists into per-slot best2 ----
        if ((t & 3) == 3) {
            const int nch = t >> 2;
#pragma unroll
            for (int m = 0; m < 2; m++) {
                const int px0 = (wm + m * 4) * 16 + g;
                const float zq0 = zsq_s[px0];
                const float zq1 = zsq_s[px0 + 8];
#pragma unroll
                for (int j = 0; j < 4; j++) {
                    const int c0 = nch * 64 + (wn * 4 + j) * 8 + 2 * tig;
                    const float e0 = esq_s[c0], e1 = esq_s[c0 + 1];
                    float dd[4];
                    dd[0] = __fadd_rn(__fadd_rn(zq0, -2.f * acc[m][j][0]), e0);
                    dd[1] = __fadd_rn(__fadd_rn(zq0, -2.f * acc[m][j][1]), e1);
                    dd[2] = __fadd_rn(__fadd_rn(zq1, -2.f * acc[m][j][2]), e0);
                    dd[3] = __fadd_rn(__fadd_rn(zq1, -2.f * acc[m][j][3]), e1);
#pragma unroll
                    for (int q = 0; q < 4; q++) {
                        const int s = m * 2 + (q >> 1);
                        const int c = c0 + (q & 1);
                        const float d = dd[q];
                        if (d < d2[s]) {
                            if (d < d1[s]) { d2[s] = d1[s]; i2[s] = i1[s]; d1[s] = d; i1[s] = c; }
                            else           { d2[s] = d;     i2[s] = c; }
                        }
                        acc[m][j][q] = 0.f;
                    }
                }
            }
        }
    }

    // ---- dump 16 candidates per pixel (8 slots x best2) into smem ----
    float* cand_d = bbuf;                   // [16][128]
    int*   cand_i = (int*)(bbuf + 2048);    // [16][128]
    __syncthreads();
#pragma unroll
    for (int s = 0; s < 4; s++) {
        const int px = (wm + (s >> 1) * 4) * 16 + g + (s & 1) * 8;
        const int sl = (wn * 4 + tig) * 2;
        cand_d[sl * 128 + px]       = d1[s];
        cand_i[sl * 128 + px]       = i1[s];
        cand_d[(sl + 1) * 128 + px] = d2[s];
        cand_i[(sl + 1) * 128 + px] = i2[s];
    }
    __syncthreads();

    // ---- exact rescore of candidates within EPS of mma-min (R4-proven order) ----
    if (tid < MT) {
        float mn = 3.4e38f;
#pragma unroll
        for (int s = 0; s < 16; s++) {
            float ad = cand_d[s * 128 + tid];
            if (ad < mn) mn = ad;
        }
        const float zq = zsq_s[tid];
        const float* zr = z_s + tid * ZS;
        float bestd = 3.4e38f;
        int   besti = 1 << 30;
#pragma unroll 1
        for (int s = 0; s < 16; s++) {
            float ad = cand_d[s * 128 + tid];
            if (ad < mn + EPS) {
                int c = cand_i[s * 128 + tid];
                const float* er = cb + (size_t)c * DDIM;
                float a = 0.f;
#pragma unroll 8
                for (int d = 0; d < DDIM; d++) a = fmaf(zr[d], __ldg(er + d), a);
                float dist = __fadd_rn(__fadd_rn(zq, -2.f * a), esq_s[c]);
                if (dist < bestd || (dist == bestd && c < besti)) { bestd = dist; besti = c; }
            }
        }
        out[pix_base + tid] = (float)besti;
    }
}

extern "C" void kernel_launch(void* const* d_in, const int* in_sizes, int n_in,
                              void* d_out, int out_size) {
    const float* a0 = (const float*)d_in[0];
    const float* a1 = (const float*)d_in[1];
    const float* z  = (in_sizes[0] > in_sizes[1]) ? a0 : a1;
    const float* cb = (in_sizes[0] > in_sizes[1]) ? a1 : a0;
    float* out = (float*)d_out;

    cudaFuncSetAttribute(vq_mma_kernel,
                         cudaFuncAttributeMaxDynamicSharedMemorySize,
                         SMEM_FLOATS * 4);

    prep_kernel<<<2, 256>>>(cb);
    vq_mma_kernel<<<NPIX / MT, THREADS, SMEM_FLOATS * 4>>>(z, cb, out);
}

// round 11
// speedup vs baseline: 1.1005x; 1.1005x over previous
#include <cuda_runtime.h>
#include <cstdint>

#define NPIX 65536
#define DDIM 256
#define KCODES 512
#define MT 128
#define THREADS 512
#define ZS 268                // z_s row stride (floats)
#define Z_OFF 0
#define B_OFF 34304           // 2 x 8192-float cp.async buffers
#define ZSQ_OFF 50688
#define ESQ_OFF 50816
#define SMEM_FLOATS 51328     // 205,312 bytes
#define EPS 2e-4f             // rescue window (provable bound ~6.6e-5)

__device__ float g_esq[KCODES];
// B fragments: [tt(32)][ks(8)][nt8(8)][lane(32)][bh0,bh1,bl0,bl1]
__device__ __align__(16) float e_frag[32 * 8192];

static __device__ __forceinline__ uint32_t smem_u32(const void* p) {
    uint32_t a;
    asm("{ .reg .u64 t; cvta.to.shared.u64 t, %1; cvt.u32.u64 %0, t; }" : "=r"(a) : "l"(p));
    return a;
}
static __device__ __forceinline__ uint32_t f2tf32(float v) {
    uint32_t r;
    asm("cvt.rna.tf32.f32 %0, %1;" : "=r"(r) : "f"(v));
    return r;
}
static __device__ __forceinline__ void mma_tf32(float* c, const uint32_t* a,
                                                uint32_t b0, uint32_t b1) {
    asm volatile("mma.sync.aligned.m16n8k8.row.col.f32.tf32.tf32.f32 "
                 "{%0,%1,%2,%3}, {%4,%5,%6,%7}, {%8,%9}, {%0,%1,%2,%3};"
                 : "+f"(c[0]), "+f"(c[1]), "+f"(c[2]), "+f"(c[3])
                 : "r"(a[0]), "r"(a[1]), "r"(a[2]), "r"(a[3]), "r"(b0), "r"(b1));
}
#define CP_ASYNC16(saddr, gptr) \
    asm volatile("cp.async.ca.shared.global [%0], [%1], 16;" :: "r"(saddr), "l"(gptr))
#define CP_COMMIT()  asm volatile("cp.async.commit_group;" ::: "memory")
#define CP_WAIT0()   asm volatile("cp.async.wait_group 0;" ::: "memory")

// ---- esq: reference rounding order ----
__global__ void esq_kernel(const float* __restrict__ cb) {
    int n = blockIdx.x * blockDim.x + threadIdx.x;
    if (n >= KCODES) return;
    const float4* row = (const float4*)(cb + n * DDIM);
    float sx = 0.f, sy = 0.f, sz = 0.f, sw = 0.f;
#pragma unroll
    for (int i = 0; i < DDIM / 4; i++) {
        float4 v = row[i];
        sx = __fadd_rn(sx, __fmul_rn(v.x, v.x));
        sy = __fadd_rn(sy, __fmul_rn(v.y, v.y));
        sz = __fadd_rn(sz, __fmul_rn(v.z, v.z));
        sw = __fadd_rn(sw, __fmul_rn(v.w, v.w));
    }
    g_esq[n] = __fadd_rn(__fadd_rn(sx, sy), __fadd_rn(sz, sw));
}

// ---- scatter codebook into B-fragment images (block-per-code, thread-per-d) ----
__global__ void scatter_kernel(const float* __restrict__ cb) {
    const int n = blockIdx.x;
    const int d = threadIdx.x;
    const int g = n & 7, nt8 = (n >> 3) & 7, nchq = (n >> 6) * 4;
    float v = cb[n * DDIM + d];
    uint32_t hb = f2tf32(v);
    uint32_t lb = f2tf32(v - __uint_as_float(hb));
    int tt = nchq + (d >> 6);
    int ks = (d >> 3) & 7;
    int ko = d & 7, tig = ko & 3, kh = ko >> 2;
    int lane = g * 4 + tig;
    int base = tt * 8192 + ((ks * 8 + nt8) * 32 + lane) * 4;
    e_frag[base + kh]     = __uint_as_float(hb);
    e_frag[base + 2 + kh] = __uint_as_float(lb);
}

__global__ __launch_bounds__(THREADS, 1)
void vq_mma_kernel(const float* __restrict__ z, const float* __restrict__ cb,
                   float* __restrict__ out) {
    extern __shared__ __align__(16) float smem[];
    float* z_s   = smem + Z_OFF;
    float* bbuf  = smem + B_OFF;
    float* zsq_s = smem + ZSQ_OFF;
    float* esq_s = smem + ESQ_OFF;
    const uint32_t bbuf_s = smem_u32(bbuf);

    const int tid  = threadIdx.x;
    const int warp = tid >> 5;
    const int lane = tid & 31;
    const int g    = lane >> 2;      // 0..7
    const int tig  = lane & 3;       // 0..3
    const int wm   = warp & 7;       // M-warp 0..7 -> mtile wm
    const int wn   = warp >> 3;      // N-warp 0..1 -> ntiles {wn*4..wn*4+3}

    const int pix_base = blockIdx.x * MT;
    const float* zbase = z + (size_t)(pix_base >> 10) * (DDIM * 1024) + (pix_base & 1023);

    // ---- transpose z: gmem [d][px] -> z_s[px][d] via staged buffer (stride 132) ----
    float* stage = bbuf;
    for (int db = 0; db < 8; db++) {
        const int dblk = db * 32;
        __syncthreads();
#pragma unroll
        for (int it = 0; it < 2; it++) {
            int linear = tid + THREADS * it;        // 0..1023
            int d  = linear >> 5;
            int p4 = (linear & 31) << 2;
            float4 v = *(const float4*)(zbase + (size_t)(dblk + d) * 1024 + p4);
            *(float4*)(stage + d * 132 + p4) = v;
        }
        __syncthreads();
#pragma unroll
        for (int it = 0; it < 2; it++) {
            int linear = tid + THREADS * it;        // 0..1023
            int p   = linear & 127;
            int dl4 = (linear >> 7) << 2;
            float4 w;
            w.x = stage[(dl4 + 0) * 132 + p];
            w.y = stage[(dl4 + 1) * 132 + p];
            w.z = stage[(dl4 + 2) * 132 + p];
            w.w = stage[(dl4 + 3) * 132 + p];
            *(float4*)(z_s + p * ZS + dblk + dl4) = w;
        }
    }
    __syncthreads();

    // ---- zsq (proven rounding order) + esq into smem ----
    esq_s[tid] = g_esq[tid];
    if (tid < MT) {
        const float4* zr = (const float4*)(z_s + tid * ZS);
        float sx = 0.f, sy = 0.f, sz = 0.f, sw = 0.f;
#pragma unroll
        for (int i = 0; i < DDIM / 4; i++) {
            float4 v = zr[i];
            sx = __fadd_rn(sx, __fmul_rn(v.x, v.x));
            sy = __fadd_rn(sy, __fmul_rn(v.y, v.y));
            sz = __fadd_rn(sz, __fmul_rn(v.z, v.z));
            sw = __fadd_rn(sw, __fmul_rn(v.w, v.w));
        }
        zsq_s[tid] = __fadd_rn(__fadd_rn(sx, sy), __fadd_rn(sz, sw));
    }

    // ---- prefetch B block 0 via cp.async ----
#pragma unroll
    for (int it = 0; it < 4; it++) {
        int fo = tid * 4 + it * 2048;   // float offset within 8192-float block
        CP_ASYNC16(bbuf_s + fo * 4, (const void*)(e_frag + fo));
    }
    CP_COMMIT();
    __syncthreads();

    // per-slot best2: slot s = pixel-half (0: px0, 1: px0+8)
    float d1[2], d2[2];
    int   i1[2], i2[2];
    float acc[4][4];
#pragma unroll
    for (int s = 0; s < 2; s++) { d1[s] = 3.4e38f; d2[s] = 3.4e38f; i1[s] = 0; i2[s] = 0; }
#pragma unroll
    for (int j = 0; j < 4; j++)
#pragma unroll
        for (int r = 0; r < 4; r++) acc[j][r] = 0.f;

    for (int t = 0; t < 32; t++) {
        const int buf = t & 1;
        CP_WAIT0();
        __syncthreads();
        if (t + 1 < 32) {
#pragma unroll
            for (int it = 0; it < 4; it++) {
                int fo = tid * 4 + it * 2048;
                CP_ASYNC16(bbuf_s + ((buf ^ 1) * 8192 + fo) * 4,
                           (const void*)(e_frag + (t + 1) * 8192 + fo));
            }
            CP_COMMIT();
        }

        const int kblk = (t & 3) * 64;
        const int mrow = wm * 16;
#pragma unroll
        for (int ks = 0; ks < 8; ks++) {
            const int kbase = kblk + ks * 8;
            uint32_t ah[4], al[4];
#pragma unroll
            for (int r = 0; r < 4; r++) {
                float v = z_s[(mrow + g + (r & 1) * 8) * ZS +
                              kbase + tig + (r >> 1) * 4];
                uint32_t hb = f2tf32(v);
                ah[r] = hb;
                al[r] = f2tf32(v - __uint_as_float(hb));
            }
#pragma unroll
            for (int j = 0; j < 4; j++) {
                const int nt8 = wn * 4 + j;
                uint4 bv = *(const uint4*)(bbuf + (buf * 8192) +
                                           ((ks * 8 + nt8) * 32 + lane) * 4);
                mma_tf32(acc[j], ah, bv.x, bv.y);  // hi*hi
                mma_tf32(acc[j], ah, bv.z, bv.w);  // hi*lo
                mma_tf32(acc[j], al, bv.x, bv.y);  // lo*hi
            }
        }

        // ---- end of nch: fold this K-chunk's dists into per-slot best2 ----
        if ((t & 3) == 3) {
            const int nch = t >> 2;
            const int px0 = wm * 16 + g;
            const float zq0 = zsq_s[px0];
            const float zq1 = zsq_s[px0 + 8];
#pragma unroll
            for (int j = 0; j < 4; j++) {
                const int c0 = nch * 64 + (wn * 4 + j) * 8 + 2 * tig;
                const float e0 = esq_s[c0], e1 = esq_s[c0 + 1];
                float dd[4];
                dd[0] = __fadd_rn(__fadd_rn(zq0, -2.f * acc[j][0]), e0);
                dd[1] = __fadd_rn(__fadd_rn(zq0, -2.f * acc[j][1]), e1);
                dd[2] = __fadd_rn(__fadd_rn(zq1, -2.f * acc[j][2]), e0);
                dd[3] = __fadd_rn(__fadd_rn(zq1, -2.f * acc[j][3]), e1);
#pragma unroll
                for (int q = 0; q < 4; q++) {
                    const int s = q >> 1;
                    const int c = c0 + (q & 1);
                    const float d = dd[q];
                    if (d < d2[s]) {
                        if (d < d1[s]) { d2[s] = d1[s]; i2[s] = i1[s]; d1[s] = d; i1[s] = c; }
                        else           { d2[s] = d;     i2[s] = c; }
                    }
                    acc[j][q] = 0.f;
                }
            }
        }
    }

    // ---- dump 16 candidates per pixel (8 (wn,tig) slots x best2) into smem ----
    float* cand_d = bbuf;                   // [16][128]
    int*   cand_i = (int*)(bbuf + 2048);    // [16][128]
    __syncthreads();
#pragma unroll
    for (int s = 0; s < 2; s++) {
        const int px = wm * 16 + g + s * 8;
        const int sl = (wn * 4 + tig) * 2;
        cand_d[sl * 128 + px]       = d1[s];
        cand_i[sl * 128 + px]       = i1[s];
        cand_d[(sl + 1) * 128 + px] = d2[s];
        cand_i[(sl + 1) * 128 + px] = i2[s];
    }
    __syncthreads();

    // ---- exact rescore of candidates within EPS of mma-min (R4-proven order) ----
    if (tid < MT) {
        float mn = 3.4e38f;
#pragma unroll
        for (int s = 0; s < 16; s++) {
            float ad = cand_d[s * 128 + tid];
            if (ad < mn) mn = ad;
        }
        const float zq = zsq_s[tid];
        const float* zr = z_s + tid * ZS;
        float bestd = 3.4e38f;
        int   besti = 1 << 30;
#pragma unroll 1
        for (int s = 0; s < 16; s++) {
            float ad = cand_d[s * 128 + tid];
            if (ad < mn + EPS) {
                int c = cand_i[s * 128 + tid];
                const float* er = cb + (size_t)c * DDIM;
                float a = 0.f;
#pragma unroll 8
                for (int d = 0; d < DDIM; d++) a = fmaf(zr[d], __ldg(er + d), a);
                float dist = __fadd_rn(__fadd_rn(zq, -2.f * a), esq_s[c]);
                if (dist < bestd || (dist == bestd && c < besti)) { bestd = dist; besti = c; }
            }
        }
        out[pix_base + tid] = (float)besti;
    }
}

extern "C" void kernel_launch(void* const* d_in, const int* in_sizes, int n_in,
                              void* d_out, int out_size) {
    const float* a0 = (const float*)d_in[0];
    const float* a1 = (const float*)d_in[1];
    const float* z  = (in_sizes[0] > in_sizes[1]) ? a0 : a1;
    const float* cb = (in_sizes[0] > in_sizes[1]) ? a1 : a0;
    float* out = (float*)d_out;

    cudaFuncSetAttribute(vq_mma_kernel,
                         cudaFuncAttributeMaxDynamicSharedMemorySize,
                         SMEM_FLOATS * 4);

    esq_kernel<<<2, 256>>>(cb);
    scatter_kernel<<<KCODES, DDIM>>>(cb);
    vq_mma_kernel<<<NPIX / MT, THREADS, SMEM_FLOATS * 4>>>(z, cb, out);
}

// round 12
// speedup vs baseline: 1.4381x; 1.3068x over previous
#include <cuda_runtime.h>
#include <cuda_bf16.h>
#include <cstdint>

#define NPIX 65536
#define DDIM 256
#define KCODES 512
#define MT 128
#define THREADS 512
#define ZS 268                 // z_s row stride (floats)
#define Z_OFF 0
#define B_OFF 34304            // 2 x 4096-float cp.async buffers
#define ZSQ_OFF 42496
#define ESQ_OFF 42624
#define SMEM_FLOATS 43136      // 172,544 bytes
#define EPS 2e-4f              // rescue window (bf16-split dist error <= ~1e-5)

__device__ float g_esq[KCODES];
// B fragments (bf16 hi/lo): [tt(32)][ks(4)][nt8(8)][lane(32)][b0h,b1h,b0l,b1l]
__device__ __align__(16) float e_frag[32 * 4096];

static __device__ __forceinline__ uint32_t smem_u32(const void* p) {
    uint32_t a;
    asm("{ .reg .u64 t; cvta.to.shared.u64 t, %1; cvt.u32.u64 %0, t; }" : "=r"(a) : "l"(p));
    return a;
}
// pack two f32 -> bf16x2; first operand lands in UPPER 16 bits
static __device__ __forceinline__ uint32_t bf16pack(float hi, float lo) {
    uint32_t r;
    asm("cvt.rn.bf16x2.f32 %0, %1, %2;" : "=r"(r) : "f"(hi), "f"(lo));
    return r;
}
static __device__ __forceinline__ void mma_bf16(float* c, const uint32_t* a,
                                                uint32_t b0, uint32_t b1) {
    asm volatile("mma.sync.aligned.m16n8k16.row.col.f32.bf16.bf16.f32 "
                 "{%0,%1,%2,%3}, {%4,%5,%6,%7}, {%8,%9}, {%0,%1,%2,%3};"
                 : "+f"(c[0]), "+f"(c[1]), "+f"(c[2]), "+f"(c[3])
                 : "r"(a[0]), "r"(a[1]), "r"(a[2]), "r"(a[3]), "r"(b0), "r"(b1));
}
#define CP_ASYNC16(saddr, gptr) \
    asm volatile("cp.async.ca.shared.global [%0], [%1], 16;" :: "r"(saddr), "l"(gptr))
#define CP_COMMIT()  asm volatile("cp.async.commit_group;" ::: "memory")
#define CP_WAIT0()   asm volatile("cp.async.wait_group 0;" ::: "memory")

// ---- esq: reference rounding order ----
__global__ void esq_kernel(const float* __restrict__ cb) {
    int n = blockIdx.x * blockDim.x + threadIdx.x;
    if (n >= KCODES) return;
    const float4* row = (const float4*)(cb + n * DDIM);
    float sx = 0.f, sy = 0.f, sz = 0.f, sw = 0.f;
#pragma unroll
    for (int i = 0; i < DDIM / 4; i++) {
        float4 v = row[i];
        sx = __fadd_rn(sx, __fmul_rn(v.x, v.x));
        sy = __fadd_rn(sy, __fmul_rn(v.y, v.y));
        sz = __fadd_rn(sz, __fmul_rn(v.z, v.z));
        sw = __fadd_rn(sw, __fmul_rn(v.w, v.w));
    }
    g_esq[n] = __fadd_rn(__fadd_rn(sx, sy), __fadd_rn(sz, sw));
}

// ---- scatter codebook into bf16 hi/lo B-fragment images ----
// block = code n, thread d2 handles dims (2*d2, 2*d2+1)
__global__ void scatter_kernel(const float* __restrict__ cb) {
    const int n  = blockIdx.x;
    const int d  = threadIdx.x * 2;
    const int g = n & 7, nt8 = (n >> 3) & 7, nch = n >> 6;
    float v0 = cb[n * DDIM + d];
    float v1 = cb[n * DDIM + d + 1];
    uint32_t hi = bf16pack(v1, v0);                    // lower 16 = k even
    float h0 = __bfloat162float(__float2bfloat16(v0));
    float h1 = __bfloat162float(__float2bfloat16(v1));
    uint32_t lo = bf16pack(v1 - h1, v0 - h0);
    int tt   = nch * 4 + (d >> 6);
    int ks   = (d >> 4) & 3;
    int ko   = d & 15;            // even
    int half = ko >> 3;           // 0: b0, 1: b1
    int tig  = (ko >> 1) & 3;
    int lane = g * 4 + tig;
    int base = tt * 4096 + ((ks * 8 + nt8) * 32 + lane) * 4;
    e_frag[base + half]     = __uint_as_float(hi);
    e_frag[base + 2 + half] = __uint_as_float(lo);
}

__global__ __launch_bounds__(THREADS, 1)
void vq_mma_kernel(const float* __restrict__ z, const float* __restrict__ cb,
                   float* __restrict__ out) {
    extern __shared__ __align__(16) float smem[];
    float* z_s   = smem + Z_OFF;
    float* bbuf  = smem + B_OFF;
    float* zsq_s = smem + ZSQ_OFF;
    float* esq_s = smem + ESQ_OFF;
    const uint32_t bbuf_s = smem_u32(bbuf);

    const int tid  = threadIdx.x;
    const int warp = tid >> 5;
    const int lane = tid & 31;
    const int g    = lane >> 2;      // 0..7
    const int tig  = lane & 3;       // 0..3
    const int wm   = warp & 7;       // M-warp 0..7 -> mtile wm
    const int wn   = warp >> 3;      // N-warp 0..1 -> ntiles {wn*4..wn*4+3}

    const int pix_base = blockIdx.x * MT;
    const float* zbase = z + (size_t)(pix_base >> 10) * (DDIM * 1024) + (pix_base & 1023);

    // ---- transpose z: gmem [d][px] -> z_s[px][d] via staged buffer (stride 132) ----
    float* stage = bbuf;   // 32*132 = 4224 floats <= 8192
    for (int db = 0; db < 8; db++) {
        const int dblk = db * 32;
        __syncthreads();
#pragma unroll
        for (int it = 0; it < 2; it++) {
            int linear = tid + THREADS * it;        // 0..1023
            int d  = linear >> 5;
            int p4 = (linear & 31) << 2;
            float4 v = *(const float4*)(zbase + (size_t)(dblk + d) * 1024 + p4);
            *(float4*)(stage + d * 132 + p4) = v;
        }
        __syncthreads();
#pragma unroll
        for (int it = 0; it < 2; it++) {
            int linear = tid + THREADS * it;        // 0..1023
            int p   = linear & 127;
            int dl4 = (linear >> 7) << 2;
            float4 w;
            w.x = stage[(dl4 + 0) * 132 + p];
            w.y = stage[(dl4 + 1) * 132 + p];
            w.z = stage[(dl4 + 2) * 132 + p];
            w.w = stage[(dl4 + 3) * 132 + p];
            *(float4*)(z_s + p * ZS + dblk + dl4) = w;
        }
    }
    __syncthreads();

    // ---- zsq (proven rounding order) + esq into smem ----
    esq_s[tid] = g_esq[tid];
    if (tid < MT) {
        const float4* zr = (const float4*)(z_s + tid * ZS);
        float sx = 0.f, sy = 0.f, sz = 0.f, sw = 0.f;
#pragma unroll
        for (int i = 0; i < DDIM / 4; i++) {
            float4 v = zr[i];
            sx = __fadd_rn(sx, __fmul_rn(v.x, v.x));
            sy = __fadd_rn(sy, __fmul_rn(v.y, v.y));
            sz = __fadd_rn(sz, __fmul_rn(v.z, v.z));
            sw = __fadd_rn(sw, __fmul_rn(v.w, v.w));
        }
        zsq_s[tid] = __fadd_rn(__fadd_rn(sx, sy), __fadd_rn(sz, sw));
    }

    // ---- prefetch B block 0 via cp.async (4096 floats = 16KB) ----
#pragma unroll
    for (int it = 0; it < 2; it++) {
        int fo = tid * 4 + it * 2048;
        CP_ASYNC16(bbuf_s + fo * 4, (const void*)(e_frag + fo));
    }
    CP_COMMIT();
    __syncthreads();

    // per-slot best2: slot s = pixel-half (0: px0, 1: px0+8)
    float d1[2], d2[2];
    int   i1[2], i2[2];
    float acc[4][4];
#pragma unroll
    for (int s = 0; s < 2; s++) { d1[s] = 3.4e38f; d2[s] = 3.4e38f; i1[s] = 0; i2[s] = 0; }
#pragma unroll
    for (int j = 0; j < 4; j++)
#pragma unroll
        for (int r = 0; r < 4; r++) acc[j][r] = 0.f;

    for (int t = 0; t < 32; t++) {
        const int buf = t & 1;
        CP_WAIT0();
        __syncthreads();
        if (t + 1 < 32) {
#pragma unroll
            for (int it = 0; it < 2; it++) {
                int fo = tid * 4 + it * 2048;
                CP_ASYNC16(bbuf_s + ((buf ^ 1) * 4096 + fo) * 4,
                           (const void*)(e_frag + (t + 1) * 4096 + fo));
            }
            CP_COMMIT();
        }

        const int kblk = (t & 3) * 64;
        const int mrow = wm * 16;
#pragma unroll
        for (int ks = 0; ks < 4; ks++) {           // k16 steps
            const int k0 = kblk + ks * 16 + 2 * tig;
            const float* zr0 = z_s + (mrow + g) * ZS + k0;
            const float* zr1 = z_s + (mrow + g + 8) * ZS + k0;
            float2 v00 = *(const float2*)(zr0);        // k0, k0+1
            float2 v01 = *(const float2*)(zr0 + 8);    // k0+8, k0+9
            float2 v10 = *(const float2*)(zr1);
            float2 v11 = *(const float2*)(zr1 + 8);

            uint32_t ah[4], al[4];
            ah[0] = bf16pack(v00.y, v00.x);
            ah[1] = bf16pack(v10.y, v10.x);
            ah[2] = bf16pack(v01.y, v01.x);
            ah[3] = bf16pack(v11.y, v11.x);
            float h;
            float l00x, l00y, l01x, l01y, l10x, l10y, l11x, l11y;
            h = __bfloat162float(__float2bfloat16(v00.x)); l00x = v00.x - h;
            h = __bfloat162float(__float2bfloat16(v00.y)); l00y = v00.y - h;
            h = __bfloat162float(__float2bfloat16(v01.x)); l01x = v01.x - h;
            h = __bfloat162float(__float2bfloat16(v01.y)); l01y = v01.y - h;
            h = __bfloat162float(__float2bfloat16(v10.x)); l10x = v10.x - h;
            h = __bfloat162float(__float2bfloat16(v10.y)); l10y = v10.y - h;
            h = __bfloat162float(__float2bfloat16(v11.x)); l11x = v11.x - h;
            h = __bfloat162float(__float2bfloat16(v11.y)); l11y = v11.y - h;
            al[0] = bf16pack(l00y, l00x);
            al[1] = bf16pack(l10y, l10x);
            al[2] = bf16pack(l01y, l01x);
            al[3] = bf16pack(l11y, l11x);

#pragma unroll
            for (int j = 0; j < 4; j++) {
                const int nt8 = wn * 4 + j;
                uint4 bv = *(const uint4*)(bbuf + (buf * 4096) +
                                           ((ks * 8 + nt8) * 32 + lane) * 4);
                mma_bf16(acc[j], ah, bv.x, bv.y);  // hi*hi
                mma_bf16(acc[j], ah, bv.z, bv.w);  // hi*lo
                mma_bf16(acc[j], al, bv.x, bv.y);  // lo*hi
            }
        }

        // ---- end of nch: fold this K-chunk's dists into per-slot best2 ----
        if ((t & 3) == 3) {
            const int nch = t >> 2;
            const int px0 = wm * 16 + g;
            const float zq0 = zsq_s[px0];
            const float zq1 = zsq_s[px0 + 8];
#pragma unroll
            for (int j = 0; j < 4; j++) {
                const int c0 = nch * 64 + (wn * 4 + j) * 8 + 2 * tig;
                const float e0 = esq_s[c0], e1 = esq_s[c0 + 1];
                float dd[4];
                dd[0] = __fadd_rn(__fadd_rn(zq0, -2.f * acc[j][0]), e0);
                dd[1] = __fadd_rn(__fadd_rn(zq0, -2.f * acc[j][1]), e1);
                dd[2] = __fadd_rn(__fadd_rn(zq1, -2.f * acc[j][2]), e0);
                dd[3] = __fadd_rn(__fadd_rn(zq1, -2.f * acc[j][3]), e1);
#pragma unroll
                for (int q = 0; q < 4; q++) {
                    const int s = q >> 1;
                    const int c = c0 + (q & 1);
                    const float d = dd[q];
                    if (d < d2[s]) {
                        if (d < d1[s]) { d2[s] = d1[s]; i2[s] = i1[s]; d1[s] = d; i1[s] = c; }
                        else           { d2[s] = d;     i2[s] = c; }
                    }
                    acc[j][q] = 0.f;
                }
            }
        }
    }

    // ---- dump 16 candidates per pixel (8 (wn,tig) slots x best2) into smem ----
    float* cand_d = bbuf;                   // [16][128]
    int*   cand_i = (int*)(bbuf + 2048);    // [16][128]
    __syncthreads();
#pragma unroll
    for (int s = 0; s < 2; s++) {
        const int px = wm * 16 + g + s * 8;
        const int sl = (wn * 4 + tig) * 2;
        cand_d[sl * 128 + px]       = d1[s];
        cand_i[sl * 128 + px]       = i1[s];
        cand_d[(sl + 1) * 128 + px] = d2[s];
        cand_i[(sl + 1) * 128 + px] = i2[s];
    }
    __syncthreads();

    // ---- exact rescore of candidates within EPS of mma-min (R4-proven order) ----
    if (tid < MT) {
        float mn = 3.4e38f;
#pragma unroll
        for (int s = 0; s < 16; s++) {
            float ad = cand_d[s * 128 + tid];
            if (ad < mn) mn = ad;
        }
        const float zq = zsq_s[tid];
        const float* zr = z_s + tid * ZS;
        float bestd = 3.4e38f;
        int   besti = 1 << 30;
#pragma unroll 1
        for (int s = 0; s < 16; s++) {
            float ad = cand_d[s * 128 + tid];
            if (ad < mn + EPS) {
                int c = cand_i[s * 128 + tid];
                const float* er = cb + (size_t)c * DDIM;
                float a = 0.f;
#pragma unroll 8
                for (int d = 0; d < DDIM; d++) a = fmaf(zr[d], __ldg(er + d), a);
                float dist = __fadd_rn(__fadd_rn(zq, -2.f * a), esq_s[c]);
                if (dist < bestd || (dist == bestd && c < besti)) { bestd = dist; besti = c; }
            }
        }
        out[pix_base + tid] = (float)besti;
    }
}

extern "C" void kernel_launch(void* const* d_in, const int* in_sizes, int n_in,
                              void* d_out, int out_size) {
    const float* a0 = (const float*)d_in[0];
    const float* a1 = (const float*)d_in[1];
    const float* z  = (in_sizes[0] > in_sizes[1]) ? a0 : a1;
    const float* cb = (in_sizes[0] > in_sizes[1]) ? a1 : a0;
    float* out = (float*)d_out;

    cudaFuncSetAttribute(vq_mma_kernel,
                         cudaFuncAttributeMaxDynamicSharedMemorySize,
                         SMEM_FLOATS * 4);

    esq_kernel<<<2, 256>>>(cb);
    scatter_kernel<<<KCODES, DDIM / 2>>>(cb);
    vq_mma_kernel<<<NPIX / MT, THREADS, SMEM_FLOATS * 4>>>(z, cb, out);
}

// round 13
// speedup vs baseline: 1.7173x; 1.1941x over previous
#include <cuda_runtime.h>
#include <cuda_fp16.h>
#include <cstdint>

#define NPIX 65536
#define DDIM 256
#define KCODES 512
#define MT 128
#define THREADS 512
#define ZS 268                 // z_s row stride (floats)
#define Z_OFF 0
#define B_OFF 34304            // 2 x 2048-float cp.async buffers (8KB each)
#define ZSQ_OFF 38400
#define ESQ_OFF 38528
#define SMEM_FLOATS 39040      // 156,160 bytes
#define EPS 2e-4f              // rescue window (fp16 filter dist err ~1.4e-5 rms)

__device__ float g_esq[KCODES];
// B fragments (fp16): [tt(32)][ks(4)][nt8(8)][lane(32)][b0,b1]  (f16x2 words)
__device__ __align__(16) float e_frag[32 * 2048];

static __device__ __forceinline__ uint32_t smem_u32(const void* p) {
    uint32_t a;
    asm("{ .reg .u64 t; cvta.to.shared.u64 t, %1; cvt.u32.u64 %0, t; }" : "=r"(a) : "l"(p));
    return a;
}
// pack two f32 -> f16x2; first operand lands in UPPER 16 bits (same as validated bf16pack)
static __device__ __forceinline__ uint32_t f16pack(float hi, float lo) {
    uint32_t r;
    asm("cvt.rn.f16x2.f32 %0, %1, %2;" : "=r"(r) : "f"(hi), "f"(lo));
    return r;
}
static __device__ __forceinline__ void mma_fp16(float* c, const uint32_t* a,
                                                uint32_t b0, uint32_t b1) {
    asm volatile("mma.sync.aligned.m16n8k16.row.col.f32.f16.f16.f32 "
                 "{%0,%1,%2,%3}, {%4,%5,%6,%7}, {%8,%9}, {%0,%1,%2,%3};"
                 : "+f"(c[0]), "+f"(c[1]), "+f"(c[2]), "+f"(c[3])
                 : "r"(a[0]), "r"(a[1]), "r"(a[2]), "r"(a[3]), "r"(b0), "r"(b1));
}
#define CP_ASYNC16(saddr, gptr) \
    asm volatile("cp.async.ca.shared.global [%0], [%1], 16;" :: "r"(saddr), "l"(gptr))
#define CP_COMMIT()  asm volatile("cp.async.commit_group;" ::: "memory")
#define CP_WAIT0()   asm volatile("cp.async.wait_group 0;" ::: "memory")

// ---- prep: scatter codebook into fp16 B-fragment image + esq (exact reference order) ----
// block = code n (512 blocks), 128 threads; thread d2 handles dims (2*d2, 2*d2+1)
__global__ void prep_kernel(const float* __restrict__ cb) {
    __shared__ float part[4];
    const int n = blockIdx.x;
    const int t = threadIdx.x;
    const int d = t * 2;
    const int g = n & 7, nt8 = (n >> 3) & 7, nch = n >> 6;

    float v0 = cb[n * DDIM + d];
    float v1 = cb[n * DDIM + d + 1];
    uint32_t pk = f16pack(v1, v0);          // lower 16 = k-even
    int tt   = nch * 4 + (d >> 6);
    int ks   = (d >> 4) & 3;
    int ko   = d & 15;                      // even
    int half = ko >> 3;                     // 0: b0 (k<8), 1: b1 (k>=8)
    int tig  = (ko >> 1) & 3;
    int lane = g * 4 + tig;
    e_frag[tt * 2048 + ((ks * 8 + nt8) * 32 + lane) * 2 + half] = __uint_as_float(pk);

    // esq: thread j sums dims == j (mod 4) ascending (reference lane order)
    if (t < 4) {
        float s = 0.f;
        for (int i = 0; i < DDIM / 4; i++) {
            float x = cb[n * DDIM + i * 4 + t];
            s = __fadd_rn(s, __fmul_rn(x, x));
        }
        part[t] = s;
    }
    __syncthreads();
    if (t == 0)
        g_esq[n] = __fadd_rn(__fadd_rn(part[0], part[1]), __fadd_rn(part[2], part[3]));
}

__global__ __launch_bounds__(THREADS, 1)
void vq_mma_kernel(const float* __restrict__ z, const float* __restrict__ cb,
                   float* __restrict__ out) {
    extern __shared__ __align__(16) float smem[];
    float* z_s   = smem + Z_OFF;
    float* bbuf  = smem + B_OFF;
    float* zsq_s = smem + ZSQ_OFF;
    float* esq_s = smem + ESQ_OFF;
    const uint32_t bbuf_s = smem_u32(bbuf);

    const int tid  = threadIdx.x;
    const int warp = tid >> 5;
    const int lane = tid & 31;
    const int g    = lane >> 2;      // 0..7
    const int tig  = lane & 3;       // 0..3
    const int wm   = warp & 7;       // M-warp -> mtile wm
    const int wn   = warp >> 3;      // N-warp -> ntiles {wn*4..wn*4+3}

    const int pix_base = blockIdx.x * MT;
    const float* zbase = z + (size_t)(pix_base >> 10) * (DDIM * 1024) + (pix_base & 1023);

    // ---- transpose z: gmem [d][px] -> z_s[px][d] via staged buffer (stride 132) ----
    // stage (32*132=4224 floats) overlaps bbuf+zsq/esq region; those are written after.
    float* stage = bbuf;
    for (int db = 0; db < 8; db++) {
        const int dblk = db * 32;
        __syncthreads();
#pragma unroll
        for (int it = 0; it < 2; it++) {
            int linear = tid + THREADS * it;        // 0..1023
            int d  = linear >> 5;
            int p4 = (linear & 31) << 2;
            float4 v = *(const float4*)(zbase + (size_t)(dblk + d) * 1024 + p4);
            *(float4*)(stage + d * 132 + p4) = v;
        }
        __syncthreads();
#pragma unroll
        for (int it = 0; it < 2; it++) {
            int linear = tid + THREADS * it;        // 0..1023
            int p   = linear & 127;
            int dl4 = (linear >> 7) << 2;
            float4 w;
            w.x = stage[(dl4 + 0) * 132 + p];
            w.y = stage[(dl4 + 1) * 132 + p];
            w.z = stage[(dl4 + 2) * 132 + p];
            w.w = stage[(dl4 + 3) * 132 + p];
            *(float4*)(z_s + p * ZS + dblk + dl4) = w;
        }
    }
    __syncthreads();

    // ---- zsq (proven rounding order) + esq into smem ----
    esq_s[tid] = g_esq[tid];
    if (tid < MT) {
        const float4* zr = (const float4*)(z_s + tid * ZS);
        float sx = 0.f, sy = 0.f, sz = 0.f, sw = 0.f;
#pragma unroll
        for (int i = 0; i < DDIM / 4; i++) {
            float4 v = zr[i];
            sx = __fadd_rn(sx, __fmul_rn(v.x, v.x));
            sy = __fadd_rn(sy, __fmul_rn(v.y, v.y));
            sz = __fadd_rn(sz, __fmul_rn(v.z, v.z));
            sw = __fadd_rn(sw, __fmul_rn(v.w, v.w));
        }
        zsq_s[tid] = __fadd_rn(__fadd_rn(sx, sy), __fadd_rn(sz, sw));
    }

    // ---- prefetch B block 0 via cp.async (2048 floats = 8KB) ----
    CP_ASYNC16(bbuf_s + tid * 16, (const void*)(e_frag + tid * 4));
    CP_COMMIT();
    __syncthreads();

    // per-slot best2: slot s = pixel-half (0: px0, 1: px0+8)
    float d1[2], d2[2];
    int   i1[2], i2[2];
    float acc[4][4];
#pragma unroll
    for (int s = 0; s < 2; s++) { d1[s] = 3.4e38f; d2[s] = 3.4e38f; i1[s] = 0; i2[s] = 0; }
#pragma unroll
    for (int j = 0; j < 4; j++)
#pragma unroll
        for (int r = 0; r < 4; r++) acc[j][r] = 0.f;

    for (int t = 0; t < 32; t++) {
        const int buf = t & 1;
        CP_WAIT0();
        __syncthreads();
        if (t + 1 < 32) {
            CP_ASYNC16(bbuf_s + ((buf ^ 1) * 2048 + tid * 4) * 4,
                       (const void*)(e_frag + (t + 1) * 2048 + tid * 4));
            CP_COMMIT();
        }

        const int kblk = (t & 3) * 64;
        const int mrow = wm * 16;
#pragma unroll
        for (int ks = 0; ks < 4; ks++) {           // k16 steps
            const int k0 = kblk + ks * 16 + 2 * tig;
            const float* zr0 = z_s + (mrow + g) * ZS + k0;
            const float* zr1 = z_s + (mrow + g + 8) * ZS + k0;
            float2 v00 = *(const float2*)(zr0);        // k0, k0+1
            float2 v01 = *(const float2*)(zr0 + 8);    // k0+8, k0+9
            float2 v10 = *(const float2*)(zr1);
            float2 v11 = *(const float2*)(zr1 + 8);

            uint32_t ah[4];
            ah[0] = f16pack(v00.y, v00.x);
            ah[1] = f16pack(v10.y, v10.x);
            ah[2] = f16pack(v01.y, v01.x);
            ah[3] = f16pack(v11.y, v11.x);

#pragma unroll
            for (int j = 0; j < 4; j++) {
                const int nt8 = wn * 4 + j;
                float2 bv = *(const float2*)(bbuf + (buf * 2048) +
                                             ((ks * 8 + nt8) * 32 + lane) * 2);
                mma_fp16(acc[j], ah, __float_as_uint(bv.x), __float_as_uint(bv.y));
            }
        }

        // ---- end of nch: fold this K-chunk's dists into per-slot best2 ----
        if ((t & 3) == 3) {
            const int nch = t >> 2;
            const int px0 = wm * 16 + g;
            const float zq0 = zsq_s[px0];
            const float zq1 = zsq_s[px0 + 8];
#pragma unroll
            for (int j = 0; j < 4; j++) {
                const int c0 = nch * 64 + (wn * 4 + j) * 8 + 2 * tig;
                const float e0 = esq_s[c0], e1 = esq_s[c0 + 1];
                float dd[4];
                dd[0] = __fadd_rn(__fadd_rn(zq0, -2.f * acc[j][0]), e0);
                dd[1] = __fadd_rn(__fadd_rn(zq0, -2.f * acc[j][1]), e1);
                dd[2] = __fadd_rn(__fadd_rn(zq1, -2.f * acc[j][2]), e0);
                dd[3] = __fadd_rn(__fadd_rn(zq1, -2.f * acc[j][3]), e1);
#pragma unroll
                for (int q = 0; q < 4; q++) {
                    const int s = q >> 1;
                    const int c = c0 + (q & 1);
                    const float d = dd[q];
                    if (d < d2[s]) {
                        if (d < d1[s]) { d2[s] = d1[s]; i2[s] = i1[s]; d1[s] = d; i1[s] = c; }
                        else           { d2[s] = d;     i2[s] = c; }
                    }
                    acc[j][q] = 0.f;
                }
            }
        }
    }

    // ---- dump 16 candidates per pixel (8 (wn,tig) slots x best2) into smem ----
    float* cand_d = bbuf;                   // [16][128]
    int*   cand_i = (int*)(bbuf + 2048);    // [16][128]
    __syncthreads();
#pragma unroll
    for (int s = 0; s < 2; s++) {
        const int px = wm * 16 + g + s * 8;
        const int sl = (wn * 4 + tig) * 2;
        cand_d[sl * 128 + px]       = d1[s];
        cand_i[sl * 128 + px]       = i1[s];
        cand_d[(sl + 1) * 128 + px] = d2[s];
        cand_i[(sl + 1) * 128 + px] = i2[s];
    }
    __syncthreads();

    // ---- exact rescore of candidates within EPS of mma-min (R4-proven order) ----
    if (tid < MT) {
        float mn = 3.4e38f;
#pragma unroll
        for (int s = 0; s < 16; s++) {
            float ad = cand_d[s * 128 + tid];
            if (ad < mn) mn = ad;
        }
        const float zq = zsq_s[tid];
        const float* zr = z_s + tid * ZS;
        float bestd = 3.4e38f;
        int   besti = 1 << 30;
#pragma unroll 1
        for (int s = 0; s < 16; s++) {
            float ad = cand_d[s * 128 + tid];
            if (ad < mn + EPS) {
                int c = cand_i[s * 128 + tid];
                const float* er = cb + (size_t)c * DDIM;
                float a = 0.f;
#pragma unroll 8
                for (int d = 0; d < DDIM; d++) a = fmaf(zr[d], __ldg(er + d), a);
                float dist = __fadd_rn(__fadd_rn(zq, -2.f * a), esq_s[c]);
                if (dist < bestd || (dist == bestd && c < besti)) { bestd = dist; besti = c; }
            }
        }
        out[pix_base + tid] = (float)besti;
    }
}

extern "C" void kernel_launch(void* const* d_in, const int* in_sizes, int n_in,
                              void* d_out, int out_size) {
    const float* a0 = (const float*)d_in[0];
    const float* a1 = (const float*)d_in[1];
    const float* z  = (in_sizes[0] > in_sizes[1]) ? a0 : a1;
    const float* cb = (in_sizes[0] > in_sizes[1]) ? a1 : a0;
    float* out = (float*)d_out;

    cudaFuncSetAttribute(vq_mma_kernel,
                         cudaFuncAttributeMaxDynamicSharedMemorySize,
                         SMEM_FLOATS * 4);

    prep_kernel<<<KCODES, DDIM / 2>>>(cb);
    vq_mma_kernel<<<NPIX / MT, THREADS, SMEM_FLOATS * 4>>>(z, cb, out);
}